// round 13
// baseline (speedup 1.0000x reference)
#include <cuda_runtime.h>
#include <cuda_fp16.h>

// SSIM loss, single fused kernel, fp16 conv datapath, CENTERED fields,
// packed-f32x2 epilogue.
// u' = p+t-1, v = p-t. Conv fields X=(u',v), Y=(u'^2,v^2) as half2.
// Weights sum to 1: A=A'+1, C=C'+2A'+1 recovered in fp32 epilogue.
// R13 = R11 structure exactly (131.6us schedule) + SSIM epilogue computed
// on f32x2 pairs (add/mul/fma.rn.f32x2, PTX-only): ~18 -> ~9.5 fma-pipe
// ops/pixel in the epilogue, ~13% less work on the binding fma pipe.

#define TW    32
#define TH    128
#define HALO  5
#define EW    42
#define EH    138
#define XP    43              // pitch (half2) input tile
#define HP    33              // pitch (8B rec) h-pass array

#define IMG_H 512
#define IMG_W 512
#define N_PLANES 96
#define GX    16
#define GY    4
#define NBLK  (GX*GY*N_PLANES)   // 6144
#define N_PIX 25165824.0

#define SX_OFF   0
#define HQ_OFF   (EH*XP*4)             // 23736
#define RED_OFF  (HQ_OFF + EH*HP*8)    // 60168
#define SMEM_TOTAL (RED_OFF + 16*4 + 16)   // ~60.2KB -> 3 blocks/SM

typedef unsigned long long ull;

__device__ constexpr float GW[11] = {
    0.00102838f, 0.00759877f, 0.03600077f, 0.10936071f, 0.21300553f,
    0.26601175f,
    0.21300553f, 0.10936071f, 0.03600077f, 0.00759877f, 0.00102838f
};

struct __align__(8) HQrec { __half2 ab; __half2 cd; };

__device__ float g_part[NBLK];
__device__ unsigned int g_count;

// ---- f32x2 packed helpers (sm_100+ PTX) ----
__device__ __forceinline__ ull pk2f(float lo, float hi) {
    ull r;
    asm("mov.b64 %0, {%1, %2};" : "=l"(r) : "f"(lo), "f"(hi));
    return r;
}
__device__ __forceinline__ void upk2f(float& lo, float& hi, ull v) {
    asm("mov.b64 {%0, %1}, %2;" : "=f"(lo), "=f"(hi) : "l"(v));
}
__device__ __forceinline__ ull add2f(ull a, ull b) {
    ull d; asm("add.rn.f32x2 %0, %1, %2;" : "=l"(d) : "l"(a), "l"(b)); return d;
}
__device__ __forceinline__ ull mul2f(ull a, ull b) {
    ull d; asm("mul.rn.f32x2 %0, %1, %2;" : "=l"(d) : "l"(a), "l"(b)); return d;
}
__device__ __forceinline__ ull fma2f(ull a, ull b, ull c) {
    ull d; asm("fma.rn.f32x2 %0, %1, %2, %3;" : "=l"(d) : "l"(a), "l"(b), "l"(c)); return d;
}

__global__ __launch_bounds__(512, 3)
void ssim_tile_kernel(const float* __restrict__ pred,
                      const float* __restrict__ targ,
                      float* __restrict__ out)
{
    extern __shared__ char smem[];
    __half2 (*sX)[XP] = (__half2(*)[XP])(smem + SX_OFF);
    HQrec   (*hQ)[HP] = (HQrec(*)[HP])(smem + HQ_OFF);
    float* red    = (float*)(smem + RED_OFF);
    int* lastflag = (int*)(smem + RED_OFF + 16*4);

    const int tid = threadIdx.x;
    const int ty0 = blockIdx.y * TH;
    const int tx0 = blockIdx.x * TW;
    const size_t pbase = (size_t)blockIdx.z * (IMG_H * IMG_W);

    // ---- load halo tile, compute centered (u', v), store half2 ----
    #pragma unroll
    for (int it = 0; it < 12; it++) {
        int idx = tid + it * 512;
        if (idx < EH * EW) {
            int r = idx / EW;
            int c = idx - r * EW;
            int gy = ty0 + r - HALO;
            int gx = tx0 + c - HALO;
            bool ok = ((unsigned)gy < (unsigned)IMG_H) & ((unsigned)gx < (unsigned)IMG_W);
            float a = 0.f, b = 0.f;
            if (ok) {
                size_t off = pbase + (size_t)gy * IMG_W + gx;
                a = pred[off];
                b = targ[off];
            }
            sX[r][c] = __floats2half2_rn(a + b - 1.0f, a - b);
        }
    }
    __syncthreads();

    // ---- horizontal pass: 138 rows x 8 quad-groups = 1104 items ----
    #pragma unroll
    for (int it = 0; it < 3; it++) {
        int g = tid + it * 512;
        if (g < EH * (TW / 4)) {
            const int r  = g >> 3;
            const int c0 = (g & 7) * 4;
            __half2 aX[4], aY[4];
            #pragma unroll
            for (int j = 0; j < 4; j++) {
                aX[j] = __floats2half2_rn(0.f, 0.f);
                aY[j] = aX[j];
            }

            #pragma unroll
            for (int i = 0; i < 14; i++) {
                __half2 X = sX[r][c0 + i];
                __half2 Y = __hmul2(X, X);
                #pragma unroll
                for (int j = 0; j < 4; j++) {
                    int k = i - j;
                    if (k >= 0 && k <= 10) {
                        __half2 w2 = __float2half2_rn(GW[k]);
                        aX[j] = __hfma2(X, w2, aX[j]);
                        aY[j] = __hfma2(Y, w2, aY[j]);
                    }
                }
            }
            #pragma unroll
            for (int j = 0; j < 4; j++) {
                HQrec q; q.ab = aX[j]; q.cd = aY[j];
                hQ[r][c0 + j] = q;      // one STS.64
            }
        }
    }
    __syncthreads();

    // ---- vertical pass + SSIM: thread -> (x, 8 rows as 2 rounds of 4) ----
    const int x   = tid & 31;
    const int yb  = (tid >> 5) * 8;    // 0..120

    float lsum = 0.f;

    #pragma unroll 1
    for (int rd = 0; rd < 2; rd++) {
        const int y0 = yb + rd * 4;

        __half2 vX[4], vY[4];
        #pragma unroll
        for (int j = 0; j < 4; j++) {
            vX[j] = __floats2half2_rn(0.f, 0.f);
            vY[j] = vX[j];
        }

        #pragma unroll
        for (int i = 0; i < 14; i++) {
            HQrec q = hQ[y0 + i][x];   // one LDS.64 per tap
            #pragma unroll
            for (int j = 0; j < 4; j++) {
                int k = i - j;
                if (k >= 0 && k <= 10) {
                    __half2 w2 = __float2half2_rn(GW[k]);
                    vX[j] = __hfma2(q.ab, w2, vX[j]);
                    vY[j] = __hfma2(q.cd, w2, vY[j]);
                }
            }
        }

        // ---- packed f32x2 epilogue: pairs (0,1) and (2,3) ----
        const ull ONE  = pk2f(1.0f, 1.0f);
        const ull HLF  = pk2f(0.5f, 0.5f);
        const ull NEG1 = pk2f(-1.0f, -1.0f);
        const ull C1P  = pk2f(1e-4f, 1e-4f);
        const ull C2P  = pk2f(9e-4f, 9e-4f);
        const ull EPSP = pk2f(1e-8f, 1e-8f);

        #pragma unroll
        for (int pj = 0; pj < 2; pj++) {
            const int j0 = pj * 2;
            ull AP = pk2f(__low2float(vX[j0]),  __low2float(vX[j0 + 1]));   // A'
            ull BP = pk2f(__high2float(vX[j0]), __high2float(vX[j0 + 1]));  // B
            ull CP = pk2f(__low2float(vY[j0]),  __low2float(vY[j0 + 1]));   // C'
            ull DP = pk2f(__high2float(vY[j0]), __high2float(vY[j0 + 1]));  // D

            ull t    = add2f(AP, ONE);            // A = A'+1
            ull A2   = mul2f(t, t);               // A^2
            ull B2   = mul2f(BP, BP);
            ull dAB  = fma2f(B2, NEG1, A2);       // A^2 - B^2
            ull t2m  = mul2f(dAB, HLF);           // 2*m12
            ull sAB  = add2f(A2, B2);
            ull msum = mul2f(sAB, HLF);           // m1s+m2s
            ull e    = add2f(AP, HLF);            // A' + 0.5
            ull cdd  = fma2f(DP, NEG1, CP);       // C' - D
            ull t2s  = fma2f(cdd, HLF, e);
            t2s      = fma2f(t2m, NEG1, t2s);     // 2*s12
            ull cds  = add2f(CP, DP);
            ull ssum = fma2f(cds, HLF, e);
            ssum     = fma2f(msum, NEG1, ssum);   // s1+s2
            ull num  = mul2f(add2f(t2m, C1P), add2f(t2s, C2P));
            ull den  = fma2f(add2f(msum, C1P), add2f(ssum, C2P), EPSP);

            float n0, n1, d0, d1;
            upk2f(n0, n1, num);
            upk2f(d0, d1, den);
            lsum += __fdividef(n0, d0) + __fdividef(n1, d1);
        }
    }

    // ---- block reduce, unique partial slot ----
    #pragma unroll
    for (int o = 16; o; o >>= 1)
        lsum += __shfl_xor_sync(0xffffffffu, lsum, o);
    if ((tid & 31) == 0) red[tid >> 5] = lsum;
    __syncthreads();

    if (tid == 0) {
        float s = 0.f;
        #pragma unroll
        for (int w = 0; w < 16; w++) s += red[w];
        int bid = (blockIdx.z * GY + blockIdx.y) * GX + blockIdx.x;
        g_part[bid] = s;
        __threadfence();
        unsigned int prev = atomicAdd(&g_count, 1u);
        *lastflag = (prev == NBLK - 1) ? 1 : 0;
    }
    __syncthreads();

    // ---- last block: final reduction over all partials ----
    if (*lastflag) {
        __threadfence();
        const float4* p4 = (const float4*)g_part;
        float s = 0.f;
        #pragma unroll
        for (int it = 0; it < 3; it++) {
            float4 v = p4[tid + it * 512];
            s += (v.x + v.y) + (v.z + v.w);
        }
        #pragma unroll
        for (int o = 16; o; o >>= 1)
            s += __shfl_xor_sync(0xffffffffu, s, o);
        if ((tid & 31) == 0) red[tid >> 5] = s;
        __syncthreads();
        if (tid == 0) {
            float t = 0.f;
            #pragma unroll
            for (int w = 0; w < 16; w++) t += red[w];
            out[0] = (float)(1.0 - (double)t * (1.0 / N_PIX));
            g_count = 0;   // self-reset for next graph replay
        }
    }
}

extern "C" void kernel_launch(void* const* d_in, const int* in_sizes, int n_in,
                              void* d_out, int out_size)
{
    const float* pred = (const float*)d_in[0];
    const float* targ = (const float*)d_in[1];

    cudaFuncSetAttribute(ssim_tile_kernel,
                         cudaFuncAttributeMaxDynamicSharedMemorySize, SMEM_TOTAL);
    dim3 grid(GX, GY, N_PLANES);   // 16 x 4 x 96
    ssim_tile_kernel<<<grid, 512, SMEM_TOTAL>>>(pred, targ, (float*)d_out);
}

// round 14
// speedup vs baseline: 1.0797x; 1.0797x over previous
#include <cuda_runtime.h>
#include <cuda_fp16.h>

// SSIM loss, single fused kernel, fp16 datapath with CENTERED fields.
// u' = p+t-1 (zero-mean), v = p-t. Conv fields X=(u',v), Y=(u'^2,v^2) as
// half2 -> all fp16-accumulated quantities are O(0.1): no cancellation.
// Weights sum to 1: A=A'+1, C=C'+2A'+1, recovered exactly in fp32 epilogue.
// R14 = R11 (131.6us, regs 40, 3 CTA/SM) + subtractive trims only:
//  - h-pass taps loaded as 7 aligned LDS.64 (XP=44) instead of 14 LDS.32
//  - interior blocks skip halo bounds predicates (uniform branch)
//  - h-pass iterations 0,1 statically unguarded (full by construction)

#define TW    32
#define TH    128
#define HALO  5
#define EW    42
#define EH    138
#define XP    44              // pitch (half2), EVEN -> 8B-aligned pair loads
#define HP    33              // pitch (8B rec) h-pass array

#define IMG_H 512
#define IMG_W 512
#define N_PLANES 96
#define GX    16
#define GY    4
#define NBLK  (GX*GY*N_PLANES)   // 6144
#define N_PIX 25165824.0

#define SX_OFF   0
#define HQ_OFF   (EH*XP*4)             // 24288
#define RED_OFF  (HQ_OFF + EH*HP*8)    // 60720
#define SMEM_TOTAL (RED_OFF + 16*4 + 16)   // ~59.4KB -> 3 blocks/SM

typedef unsigned long long ull;

__device__ constexpr float GW[11] = {
    0.00102838f, 0.00759877f, 0.03600077f, 0.10936071f, 0.21300553f,
    0.26601175f,
    0.21300553f, 0.10936071f, 0.03600077f, 0.00759877f, 0.00102838f
};

struct __align__(8) HQrec { __half2 ab; __half2 cd; };

__device__ float g_part[NBLK];
__device__ unsigned int g_count;

__global__ __launch_bounds__(512, 3)
void ssim_tile_kernel(const float* __restrict__ pred,
                      const float* __restrict__ targ,
                      float* __restrict__ out)
{
    extern __shared__ char smem[];
    __half2 (*sX)[XP] = (__half2(*)[XP])(smem + SX_OFF);
    HQrec   (*hQ)[HP] = (HQrec(*)[HP])(smem + HQ_OFF);
    float* red    = (float*)(smem + RED_OFF);
    int* lastflag = (int*)(smem + RED_OFF + 16*4);

    const int tid = threadIdx.x;
    const int ty0 = blockIdx.y * TH;
    const int tx0 = blockIdx.x * TW;
    const size_t pbase = (size_t)blockIdx.z * (IMG_H * IMG_W);

    // ---- load halo tile, compute centered (u', v), store half2 ----
    const bool interior = (blockIdx.x != 0) & (blockIdx.x != GX - 1) &
                          (blockIdx.y != 0) & (blockIdx.y != GY - 1);
    if (interior) {
        #pragma unroll
        for (int it = 0; it < 12; it++) {
            int idx = tid + it * 512;
            if (idx < EH * EW) {
                int r = idx / EW;
                int c = idx - r * EW;
                size_t off = pbase + (size_t)(ty0 + r - HALO) * IMG_W
                           + (tx0 + c - HALO);
                float a = pred[off];
                float b = targ[off];
                sX[r][c] = __floats2half2_rn(a + b - 1.0f, a - b);
            }
        }
    } else {
        #pragma unroll
        for (int it = 0; it < 12; it++) {
            int idx = tid + it * 512;
            if (idx < EH * EW) {
                int r = idx / EW;
                int c = idx - r * EW;
                int gy = ty0 + r - HALO;
                int gx = tx0 + c - HALO;
                bool ok = ((unsigned)gy < (unsigned)IMG_H) &
                          ((unsigned)gx < (unsigned)IMG_W);
                float a = 0.f, b = 0.f;
                if (ok) {
                    size_t off = pbase + (size_t)gy * IMG_W + gx;
                    a = pred[off];
                    b = targ[off];
                }
                sX[r][c] = __floats2half2_rn(a + b - 1.0f, a - b);
            }
        }
    }
    __syncthreads();

    // ---- horizontal pass: 138 rows x 8 quad-groups = 1104 items ----
    #pragma unroll
    for (int it = 0; it < 3; it++) {
        int g = tid + it * 512;
        if (it < 2 || g < EH * (TW / 4)) {   // it<2 statically full
            const int r  = g >> 3;
            const int c0 = (g & 7) * 4;
            __half2 aX[4], aY[4];
            #pragma unroll
            for (int j = 0; j < 4; j++) {
                aX[j] = __floats2half2_rn(0.f, 0.f);
                aY[j] = aX[j];
            }

            // 14 taps as 7 aligned 8B pair-loads (r*XP + c0 is even)
            const ull* rowp = (const ull*)(&sX[r][c0]);
            #pragma unroll
            for (int ip = 0; ip < 7; ip++) {
                ull pr = rowp[ip];
                __half2 X0 = ((const __half2*)&pr)[0];
                __half2 X1 = ((const __half2*)&pr)[1];
                __half2 Y0 = __hmul2(X0, X0);
                __half2 Y1 = __hmul2(X1, X1);
                #pragma unroll
                for (int j = 0; j < 4; j++) {
                    int k0 = 2 * ip - j;
                    if (k0 >= 0 && k0 <= 10) {
                        __half2 w2 = __float2half2_rn(GW[k0]);
                        aX[j] = __hfma2(X0, w2, aX[j]);
                        aY[j] = __hfma2(Y0, w2, aY[j]);
                    }
                    int k1 = 2 * ip + 1 - j;
                    if (k1 >= 0 && k1 <= 10) {
                        __half2 w2 = __float2half2_rn(GW[k1]);
                        aX[j] = __hfma2(X1, w2, aX[j]);
                        aY[j] = __hfma2(Y1, w2, aY[j]);
                    }
                }
            }
            #pragma unroll
            for (int j = 0; j < 4; j++) {
                HQrec q; q.ab = aX[j]; q.cd = aY[j];
                hQ[r][c0 + j] = q;      // one STS.64
            }
        }
    }
    __syncthreads();

    // ---- vertical pass + SSIM: thread -> (x, 8 rows as 2 rounds of 4) ----
    const int x   = tid & 31;
    const int yb  = (tid >> 5) * 8;    // 0..120

    float lsum = 0.f;
    const float C1 = 1e-4f;
    const float C2 = 9e-4f;

    #pragma unroll 1
    for (int rd = 0; rd < 2; rd++) {
        const int y0 = yb + rd * 4;

        __half2 vX[4], vY[4];
        #pragma unroll
        for (int j = 0; j < 4; j++) {
            vX[j] = __floats2half2_rn(0.f, 0.f);
            vY[j] = vX[j];
        }

        #pragma unroll
        for (int i = 0; i < 14; i++) {
            HQrec q = hQ[y0 + i][x];   // one LDS.64 per tap
            #pragma unroll
            for (int j = 0; j < 4; j++) {
                int k = i - j;
                if (k >= 0 && k <= 10) {
                    __half2 w2 = __float2half2_rn(GW[k]);
                    vX[j] = __hfma2(q.ab, w2, vX[j]);
                    vY[j] = __hfma2(q.cd, w2, vY[j]);
                }
            }
        }

        #pragma unroll
        for (int j = 0; j < 4; j++) {
            float Ap = __low2float(vX[j]);    // A' = A - 1
            float B  = __high2float(vX[j]);
            float Cp = __low2float(vY[j]);    // C' = C - 2A' - 1
            float Dv = __high2float(vY[j]);
            float A2 = fmaf(Ap, Ap + 2.0f, 1.0f);   // A^2
            float B2 = B * B;
            float t2m12 = (A2 - B2) * 0.5f;
            float msum  = (A2 + B2) * 0.5f;
            float e = Ap + 0.5f;                    // (C-D)/2 recovery term
            float t2s12 = (Cp - Dv) * 0.5f + e - t2m12;
            float ssum  = (Cp + Dv) * 0.5f + e - msum;
            float num = (t2m12 + C1) * (t2s12 + C2);
            float den = (msum + C1) * (ssum + C2) + 1e-8f;
            lsum += __fdividef(num, den);
        }
    }

    // ---- block reduce, unique partial slot ----
    #pragma unroll
    for (int o = 16; o; o >>= 1)
        lsum += __shfl_xor_sync(0xffffffffu, lsum, o);
    if ((tid & 31) == 0) red[tid >> 5] = lsum;
    __syncthreads();

    if (tid == 0) {
        float s = 0.f;
        #pragma unroll
        for (int w = 0; w < 16; w++) s += red[w];
        int bid = (blockIdx.z * GY + blockIdx.y) * GX + blockIdx.x;
        g_part[bid] = s;
        __threadfence();
        unsigned int prev = atomicAdd(&g_count, 1u);
        *lastflag = (prev == NBLK - 1) ? 1 : 0;
    }
    __syncthreads();

    // ---- last block: final reduction over all partials ----
    if (*lastflag) {
        __threadfence();
        const float4* p4 = (const float4*)g_part;
        float s = 0.f;
        #pragma unroll
        for (int it = 0; it < 3; it++) {
            float4 v = p4[tid + it * 512];
            s += (v.x + v.y) + (v.z + v.w);
        }
        #pragma unroll
        for (int o = 16; o; o >>= 1)
            s += __shfl_xor_sync(0xffffffffu, s, o);
        if ((tid & 31) == 0) red[tid >> 5] = s;
        __syncthreads();
        if (tid == 0) {
            float t = 0.f;
            #pragma unroll
            for (int w = 0; w < 16; w++) t += red[w];
            out[0] = (float)(1.0 - (double)t * (1.0 / N_PIX));
            g_count = 0;   // self-reset for next graph replay
        }
    }
}

extern "C" void kernel_launch(void* const* d_in, const int* in_sizes, int n_in,
                              void* d_out, int out_size)
{
    const float* pred = (const float*)d_in[0];
    const float* targ = (const float*)d_in[1];

    cudaFuncSetAttribute(ssim_tile_kernel,
                         cudaFuncAttributeMaxDynamicSharedMemorySize, SMEM_TOTAL);
    dim3 grid(GX, GY, N_PLANES);   // 16 x 4 x 96
    ssim_tile_kernel<<<grid, 512, SMEM_TOTAL>>>(pred, targ, (float*)d_out);
}